// round 15
// baseline (speedup 1.0000x reference)
#include <cuda_runtime.h>
#include <stdint.h>

// ---------------- Problem constants (match reference setup) ----------------
constexpr int NB    = 8;
constexpr int G     = 69;
constexpr int WIN_X = 12, WIN_Y = 12, WIN_Z = 32;
constexpr int SHX = WIN_X / 2, SHY = WIN_Y / 2, SHZ = WIN_Z / 2;  // 6,6,16
constexpr int MWX = 44, MWY = 44, MWZ = 2;
constexpr int MPS = MWX * MWY * MWZ;            // 3872
constexpr int VOL = WIN_X * WIN_Y * WIN_Z;      // 4608

constexpr long long KEYS = (long long)NB * MPS * VOL;  // 142,737,408
constexpr int WORDS = (int)(KEYS / 32);                // 4,460,544

constexpr int BLOCK = 256;
constexpr int ITEMS = 8;
constexpr int WPB   = BLOCK * ITEMS;     // 2048 words per scan block
constexpr int NBLK  = WORDS / WPB;       // 2178 (exact)

constexpr int MAXN = 1 << 22;
constexpr int MAXC = 160;                // candidate window for N solver

// ---------------- Static device scratch (zero-initialized at load) --------
// Invariant: g_bitX/g_bitY all-zero on entry (zero-init at load; restored by
// k_scanf clear-behind each run). g_stat/g_tick cleared by k_clear_stat.
__device__ __align__(128) uint32_t g_bitX[WORDS];
__device__ __align__(128) uint32_t g_bitY[WORDS];
__device__ __align__(128) uint2    g_cmbX[WORDS];   // {bits, exclusive scan}
__device__ __align__(128) uint2    g_cmbY[WORDS];
__device__ unsigned long long g_stat[2][NBLK];      // lookback: flag<<32|val
__device__ unsigned int g_tick[2];                  // ticket counters
__device__ int g_vx[MAXN];
__device__ int g_vy[MAXN];
__device__ int g_bs[NB + 1];
__device__ int g_bsp[NB + 1];
__device__ int g_cnt[NB];
__device__ int g_cntp[NB];
__device__ int g_N;
__device__ int g_is64;

// ---------------- Kernels ----------------

__device__ __forceinline__ int ld_batch(const int* c32, int m, bool is64) {
    return is64 ? c32[8 * m] : c32[4 * m];
}

// Detect coords dtype, then solve N from out_size == Np(N) + 3N.
__global__ void k_meta(const int* __restrict__ c32, int E, int out_size) {
    __shared__ int sh_bs[MAXC][NB];
    __shared__ uint32_t s_orr;
    __shared__ int s_is64;
    int tid = threadIdx.x;

    if (tid == 0) s_orr = 0u;
    __syncthreads();
    {
        int rows = E / 8;
        if (rows > 2048) rows = 2048;
        uint32_t orr = 0;
        for (int t = tid; t < rows * 4; t += BLOCK)
            orr |= (uint32_t)c32[2 * t + 1];
        atomicOr(&s_orr, orr);
    }
    __syncthreads();
    if (tid == 0) s_is64 = (s_orr == 0u) ? 1 : 0;
    __syncthreads();
    bool is64 = (s_is64 != 0);

    int n_std = E / 4;
    if (n_std < 1) n_std = 1;
    if (n_std > MAXN) n_std = MAXN;

    int hi = out_size / 4;
    if (hi > MAXN) hi = MAXN;
    if (hi < 1) hi = 1;
    int lo = hi - (MAXC - 2);
    if (lo < 1) lo = 1;
    int ncand = hi - lo + 1;               // slot ncand = n_std

    for (int t = tid; t < (ncand + 1) * NB; t += BLOCK) {
        int c = t >> 3, b = t & 7;
        int cand = (c == ncand) ? n_std : (lo + c);
        int l = 0, h = cand;
        while (l < h) {
            int m = (l + h) >> 1;
            if (ld_batch(c32, m, is64) < b) l = m + 1; else h = m;
        }
        sh_bs[c][b] = l;
    }
    __syncthreads();

    if (tid == 0) {
        g_is64 = s_is64;
        int sel = ncand, selN = n_std;
        long long fstd = 0;
        for (int b = 0; b < NB; b++) {
            int e = (b == NB - 1) ? n_std : sh_bs[ncand][b + 1];
            int cnt = e - sh_bs[ncand][b];
            fstd += ((cnt + G - 1) / G) * (long long)G;
        }
        fstd += 3LL * n_std;
        if (fstd != out_size) {
            for (int c = ncand - 1; c >= 0; c--) {
                int cand = lo + c;
                long long f = 0;
                for (int b = 0; b < NB; b++) {
                    int e = (b == NB - 1) ? cand : sh_bs[c][b + 1];
                    int cnt = e - sh_bs[c][b];
                    f += ((cnt + G - 1) / G) * (long long)G;
                }
                f += 3LL * cand;
                if (f == out_size) { sel = c; selN = cand; break; }
            }
        }
        g_N = selN;
        int acc = 0;
        g_bsp[0] = 0;
        for (int b = 0; b < NB; b++) {
            int s = sh_bs[sel][b];
            int e = (b == NB - 1) ? selN : sh_bs[sel][b + 1];
            g_bs[b] = s;
            int c = e - s;
            g_cnt[b] = c;
            int cp = ((c + G - 1) / G) * G;
            g_cntp[b] = cp;
            acc += cp;
            g_bsp[b + 1] = acc;
        }
        g_bs[NB] = selN;
    }
}

// Reset lookback status + tickets (35 KB, ~2 us).
__global__ void k_clear_stat() {
    int i = blockIdx.x * blockDim.x + threadIdx.x;
    if (i < NBLK) { g_stat[0][i] = 0ull; g_stat[1][i] = 0ull; }
    if (i == 0) { g_tick[0] = 0u; g_tick[1] = 0u; }
}

// Zero any output padding beyond Np + 3N (normally empty).
__global__ void k_tail(float* __restrict__ out, int out_size) {
    int end = g_bsp[NB] + 3 * g_N;
    for (int i = end + blockIdx.x * blockDim.x + threadIdx.x; i < out_size;
         i += gridDim.x * blockDim.x)
        out[i] = 0.0f;
}

// Per-point: keys, bitmap marks, win2flat at out[Np + i] (float).
__global__ void k_build(const int* __restrict__ c32,
                        float* __restrict__ out, int out_size) {
    int i = blockIdx.x * blockDim.x + threadIdx.x;
    int N = g_N;
    if (i >= N) return;
    int Np = g_bsp[NB];
    int b, z, y, x;
    if (g_is64) {
        const int* p = c32 + 8 * i;
        b = p[0]; z = p[2]; y = p[4]; x = p[6];
    } else {
        int4 c = reinterpret_cast<const int4*>(c32)[i];
        b = c.x; z = c.y; y = c.z; x = c.w;
    }
    z += SHZ; y += SHY; x += SHX;
    int wx = x / WIN_X, cx = x - wx * WIN_X;
    int wy = y / WIN_Y, cy = y - wy * WIN_Y;
    int wz = z >> 5,    cz = z & 31;
    int bwx = b * MPS + (wx * MWY + wy) * MWZ + wz;
    int bwy = b * MPS + (wy * MWX + wx) * MWZ + wz;
    int vx = bwx * VOL + (cx * WIN_Y + cy) * WIN_Z + cz;
    int vy = bwy * VOL + (cy * WIN_X + cx) * WIN_Z + cz;
    g_vx[i] = vx;
    g_vy[i] = vy;
    if (vx >= 0 && vx < (int)KEYS) atomicOr(&g_bitX[vx >> 5], 1u << (vx & 31));
    if (vy >= 0 && vy < (int)KEYS) atomicOr(&g_bitY[vy >> 5], 1u << (vy & 31));
    int dst = Np + i;
    if (dst >= 0 && dst < out_size)
        out[dst] = (float)(i + (g_bsp[b] - g_bs[b]));
}

// flat2win value for padded index j.
__device__ __forceinline__ int f2w_val(int j, const int* s_bs, const int* s_bsp,
                                       const int* s_cnt, const int* s_cntp) {
    int b = 0;
#pragma unroll
    for (int k = 1; k < NB; k++) if (j >= s_bsp[k]) b = k;
    int off  = s_bsp[b] - s_bs[b];
    int num  = s_cnt[b];
    int nump = s_cntp[b];
    int r = num % G;
    int tail = (num != nump) ? (s_bsp[b + 1] - G + r) : s_bsp[b + 1];
    if (j < tail)  return j - off;
    if (nump != G) return j - G - off;
    int t = j - tail;
    int m = num > 0 ? num : 1;
    return s_bs[b] + t % m;
}

// flat2win: 4 consecutive j per thread, float4 stores.
__global__ void k_f2w(float* __restrict__ out, int out_size) {
    __shared__ int s_bs[NB + 1], s_bsp[NB + 1], s_cnt[NB], s_cntp[NB];
    if (threadIdx.x <= NB) {
        s_bs[threadIdx.x]  = g_bs[threadIdx.x];
        s_bsp[threadIdx.x] = g_bsp[threadIdx.x];
    }
    if (threadIdx.x < NB) {
        s_cnt[threadIdx.x]  = g_cnt[threadIdx.x];
        s_cntp[threadIdx.x] = g_cntp[threadIdx.x];
    }
    __syncthreads();
    int Np = s_bsp[NB];
    int lim = Np < out_size ? Np : out_size;
    int j0 = (blockIdx.x * blockDim.x + threadIdx.x) * 4;
    if (j0 >= lim) return;
    if (j0 + 3 < lim) {
        float4 r;
        r.x = (float)f2w_val(j0 + 0, s_bs, s_bsp, s_cnt, s_cntp);
        r.y = (float)f2w_val(j0 + 1, s_bs, s_bsp, s_cnt, s_cntp);
        r.z = (float)f2w_val(j0 + 2, s_bs, s_bsp, s_cnt, s_cntp);
        r.w = (float)f2w_val(j0 + 3, s_bs, s_bsp, s_cnt, s_cntp);
        reinterpret_cast<float4*>(out)[j0 >> 2] = r;
    } else {
        for (int j = j0; j < lim; j++)
            out[j] = (float)f2w_val(j, s_bs, s_bsp, s_cnt, s_cntp);
    }
}

// Single-pass decoupled-lookback scan over the bitmaps.
// Writes fused {bits, exclusive scan} to cmb and clears bm behind itself.
__global__ void k_scanf() {
    int m = blockIdx.y;
    uint32_t* bm = m ? g_bitY : g_bitX;
    uint2* cmb   = m ? g_cmbY : g_cmbX;
    unsigned long long* stat = g_stat[m];

    // ticket: virtual block id monotone in scheduling order (deadlock-free)
    __shared__ unsigned int s_vb;
    if (threadIdx.x == 0) s_vb = atomicAdd(&g_tick[m], 1u);
    __syncthreads();
    int vb = (int)s_vb;

    int base = vb * WPB + threadIdx.x * ITEMS;
    uint4 a = reinterpret_cast<const uint4*>(bm + base)[0];
    uint4 b = reinterpret_cast<const uint4*>(bm + base)[1];
    int pc[8];
    pc[0] = __popc(a.x); pc[1] = __popc(a.y); pc[2] = __popc(a.z); pc[3] = __popc(a.w);
    pc[4] = __popc(b.x); pc[5] = __popc(b.y); pc[6] = __popc(b.z); pc[7] = __popc(b.w);
    int s = pc[0] + pc[1] + pc[2] + pc[3] + pc[4] + pc[5] + pc[6] + pc[7];

    int lane = threadIdx.x & 31, warp = threadIdx.x >> 5;
    int incl = s;
#pragma unroll
    for (int d = 1; d < 32; d <<= 1) {
        int n = __shfl_up_sync(0xFFFFFFFFu, incl, d);
        if (lane >= d) incl += n;
    }
    __shared__ int wsum[BLOCK / 32];
    if (lane == 31) wsum[warp] = incl;
    __syncthreads();
    int wofs = 0, total = 0;
#pragma unroll
    for (int k = 0; k < BLOCK / 32; k++) {
        if (k < warp) wofs += wsum[k];
        total += wsum[k];
    }
    uint32_t thr_excl = (uint32_t)(wofs + incl - s);

    // publish aggregate (or prefix for block 0)
    if (threadIdx.x == 0) {
        unsigned long long v = (vb == 0)
            ? ((2ull << 32) | (unsigned int)total)
            : ((1ull << 32) | (unsigned int)total);
        atomicExch(&stat[vb], v);
    }

    // warp-parallel lookback
    __shared__ uint32_t s_excl;
    if (threadIdx.x == 0 && vb == 0) s_excl = 0u;
    if (threadIdx.x < 32 && vb > 0) {
        uint32_t run = 0;
        int j = vb - 1;
        while (true) {
            int idx = j - lane;
            unsigned long long v;
            unsigned int flag;
            do {
                v = (idx >= 0) ? *((volatile unsigned long long*)&stat[idx])
                               : (2ull << 32);
                flag = (unsigned int)(v >> 32);
            } while (__any_sync(0xFFFFFFFFu, flag == 0u));
            unsigned int mask2 = __ballot_sync(0xFFFFFFFFu, flag == 2u);
            uint32_t val = (uint32_t)v;
            if (mask2) {
                int fl = __ffs(mask2) - 1;      // closest prefix
                uint32_t c = (lane <= fl) ? val : 0u;
#pragma unroll
                for (int d = 16; d; d >>= 1) c += __shfl_down_sync(0xFFFFFFFFu, c, d);
                if (lane == 0) run += c;
                break;
            } else {
                uint32_t c = val;
#pragma unroll
                for (int d = 16; d; d >>= 1) c += __shfl_down_sync(0xFFFFFFFFu, c, d);
                if (lane == 0) run += c;
                j -= 32;
            }
        }
        if (lane == 0) s_excl = run;
    }
    __syncthreads();
    uint32_t bexcl = s_excl;
    if (threadIdx.x == 0 && vb > 0)
        atomicExch(&stat[vb], (2ull << 32) | (unsigned int)(bexcl + (uint32_t)total));

    uint32_t excl = bexcl + thr_excl;
    uint32_t w_[8] = {a.x, a.y, a.z, a.w, b.x, b.y, b.z, b.w};
#pragma unroll
    for (int k = 0; k < 8; k++) {
        cmb[base + k] = make_uint2(w_[k], excl);
        excl += (uint32_t)pc[k];
    }
    // clear-behind: restore zero bitmap for next replay
    uint4 z = make_uint4(0u, 0u, 0u, 0u);
    reinterpret_cast<uint4*>(bm + base)[0] = z;
    reinterpret_cast<uint4*>(bm + base)[1] = z;
}

// Rank via one fused gather per map, scatter argsort results (float).
// Layout: [ f2w(Np) | w2f(N) | xmap(N) | ymap(N) ].
__global__ void k_scatter(float* __restrict__ out, int out_size) {
    int i = blockIdx.x * blockDim.x + threadIdx.x;
    int N = g_N;
    if (i >= N) return;
    int Np = g_bsp[NB];
    float fi = (float)i;
    {
        int v = g_vx[i];
        int w = v >> 5, bit = v & 31;
        uint2 c = g_cmbX[w];
        int r = (int)c.y + __popc(c.x & ((1u << bit) - 1u));
        int dst = Np + N + r;
        if (dst >= 0 && dst < out_size) out[dst] = fi;
    }
    {
        int v = g_vy[i];
        int w = v >> 5, bit = v & 31;
        uint2 c = g_cmbY[w];
        int r = (int)c.y + __popc(c.x & ((1u << bit) - 1u));
        int dst = Np + 2 * N + r;
        if (dst >= 0 && dst < out_size) out[dst] = fi;
    }
}

// ---------------- Launch ----------------
extern "C" void kernel_launch(void* const* d_in, const int* in_sizes, int n_in,
                              void* d_out, int out_size) {
    int ci = 0;
    for (int k = 1; k < n_in; k++) if (in_sizes[k] > in_sizes[ci]) ci = k;
    const int* coords = (const int*)d_in[ci];
    int E = in_sizes[ci];

    int n_launch = E / 4;
    if (out_size / 4 > n_launch) n_launch = out_size / 4;
    if (n_launch < 1) n_launch = 1;
    if (n_launch > MAXN) n_launch = MAXN;

    float* out = (float*)d_out;
    int np_max = n_launch + NB * G;

    k_meta<<<1, BLOCK>>>(coords, E, out_size);
    k_clear_stat<<<(NBLK + 255) / 256, 256>>>();
    k_tail<<<32, 256>>>(out, out_size);
    k_build<<<(n_launch + 255) / 256, 256>>>(coords, out, out_size);
    k_f2w<<<((np_max + 3) / 4 + 255) / 256, 256>>>(out, out_size);
    dim3 gscan(NBLK, 2);
    k_scanf<<<gscan, BLOCK>>>();
    k_scatter<<<(n_launch + 255) / 256, 256>>>(out, out_size);
}

// round 16
// speedup vs baseline: 1.0432x; 1.0432x over previous
#include <cuda_runtime.h>
#include <stdint.h>

// ---------------- Problem constants (match reference setup) ----------------
constexpr int NB    = 8;
constexpr int G     = 69;
constexpr int WIN_X = 12, WIN_Y = 12, WIN_Z = 32;
constexpr int SHX = WIN_X / 2, SHY = WIN_Y / 2, SHZ = WIN_Z / 2;  // 6,6,16
constexpr int MWX = 44, MWY = 44, MWZ = 2;
constexpr int MPS = MWX * MWY * MWZ;            // 3872
constexpr int VOL = WIN_X * WIN_Y * WIN_Z;      // 4608

constexpr long long KEYS = (long long)NB * MPS * VOL;  // 142,737,408
constexpr int WORDS = (int)(KEYS / 32);                // 4,460,544

constexpr int BLOCK = 256;
constexpr int ITEMS = 8;
constexpr int WPB   = BLOCK * ITEMS;     // 2048 words per scan block
constexpr int NBLK  = WORDS / WPB;       // 2178 (exact)

constexpr int MAXN = 1 << 22;
constexpr int MAXC = 160;                // candidate window for N solver

// ---------------- Static device scratch (zero-initialized at load) --------
// Invariant: g_bitX/g_bitY all-zero on entry (zero-init at load; restored by
// k_scan3 clear-behind each run).
__device__ __align__(128) uint32_t g_bitX[WORDS];
__device__ __align__(128) uint32_t g_bitY[WORDS];
__device__ __align__(128) uint2    g_cmbX[WORDS];   // {bits, exclusive scan}
__device__ __align__(128) uint2    g_cmbY[WORDS];
__device__ uint32_t g_bsumX[NBLK];
__device__ uint32_t g_bsumY[NBLK];
__device__ int g_vx[MAXN];
__device__ int g_vy[MAXN];
__device__ int g_bs[NB + 1];
__device__ int g_bsp[NB + 1];
__device__ int g_cnt[NB];
__device__ int g_cntp[NB];
__device__ int g_N;
__device__ int g_is64;

// ---------------- Kernels ----------------

__device__ __forceinline__ int ld_batch(const int* c32, int m, bool is64) {
    return is64 ? c32[8 * m] : c32[4 * m];
}

// Detect coords dtype, then solve N from out_size == Np(N) + 3N.
__global__ void k_meta(const int* __restrict__ c32, int E, int out_size) {
    __shared__ int sh_bs[MAXC][NB];
    __shared__ uint32_t s_orr;
    __shared__ int s_is64;
    int tid = threadIdx.x;

    if (tid == 0) s_orr = 0u;
    __syncthreads();
    {
        int rows = E / 8;
        if (rows > 2048) rows = 2048;
        uint32_t orr = 0;
        for (int t = tid; t < rows * 4; t += BLOCK)
            orr |= (uint32_t)c32[2 * t + 1];
        atomicOr(&s_orr, orr);
    }
    __syncthreads();
    if (tid == 0) s_is64 = (s_orr == 0u) ? 1 : 0;
    __syncthreads();
    bool is64 = (s_is64 != 0);

    int n_std = E / 4;
    if (n_std < 1) n_std = 1;
    if (n_std > MAXN) n_std = MAXN;

    int hi = out_size / 4;
    if (hi > MAXN) hi = MAXN;
    if (hi < 1) hi = 1;
    int lo = hi - (MAXC - 2);
    if (lo < 1) lo = 1;
    int ncand = hi - lo + 1;               // slot ncand = n_std

    for (int t = tid; t < (ncand + 1) * NB; t += BLOCK) {
        int c = t >> 3, b = t & 7;
        int cand = (c == ncand) ? n_std : (lo + c);
        int l = 0, h = cand;
        while (l < h) {
            int m = (l + h) >> 1;
            if (ld_batch(c32, m, is64) < b) l = m + 1; else h = m;
        }
        sh_bs[c][b] = l;
    }
    __syncthreads();

    if (tid == 0) {
        g_is64 = s_is64;
        int sel = ncand, selN = n_std;
        long long fstd = 0;
        for (int b = 0; b < NB; b++) {
            int e = (b == NB - 1) ? n_std : sh_bs[ncand][b + 1];
            int cnt = e - sh_bs[ncand][b];
            fstd += ((cnt + G - 1) / G) * (long long)G;
        }
        fstd += 3LL * n_std;
        if (fstd != out_size) {
            for (int c = ncand - 1; c >= 0; c--) {
                int cand = lo + c;
                long long f = 0;
                for (int b = 0; b < NB; b++) {
                    int e = (b == NB - 1) ? cand : sh_bs[c][b + 1];
                    int cnt = e - sh_bs[c][b];
                    f += ((cnt + G - 1) / G) * (long long)G;
                }
                f += 3LL * cand;
                if (f == out_size) { sel = c; selN = cand; break; }
            }
        }
        g_N = selN;
        int acc = 0;
        g_bsp[0] = 0;
        for (int b = 0; b < NB; b++) {
            int s = sh_bs[sel][b];
            int e = (b == NB - 1) ? selN : sh_bs[sel][b + 1];
            g_bs[b] = s;
            int c = e - s;
            g_cnt[b] = c;
            int cp = ((c + G - 1) / G) * G;
            g_cntp[b] = cp;
            acc += cp;
            g_bsp[b + 1] = acc;
        }
        g_bs[NB] = selN;
    }
}

// Zero any output padding beyond Np + 3N (normally empty).
__global__ void k_tail(float* __restrict__ out, int out_size) {
    int end = g_bsp[NB] + 3 * g_N;
    for (int i = end + blockIdx.x * blockDim.x + threadIdx.x; i < out_size;
         i += gridDim.x * blockDim.x)
        out[i] = 0.0f;
}

// Per-point: keys, bitmap marks, win2flat at out[Np + i] (float).
__global__ void k_build(const int* __restrict__ c32,
                        float* __restrict__ out, int out_size) {
    int i = blockIdx.x * blockDim.x + threadIdx.x;
    int N = g_N;
    if (i >= N) return;
    int Np = g_bsp[NB];
    int b, z, y, x;
    if (g_is64) {
        const int* p = c32 + 8 * i;
        b = p[0]; z = p[2]; y = p[4]; x = p[6];
    } else {
        int4 c = reinterpret_cast<const int4*>(c32)[i];
        b = c.x; z = c.y; y = c.z; x = c.w;
    }
    z += SHZ; y += SHY; x += SHX;
    int wx = x / WIN_X, cx = x - wx * WIN_X;
    int wy = y / WIN_Y, cy = y - wy * WIN_Y;
    int wz = z >> 5,    cz = z & 31;
    int bwx = b * MPS + (wx * MWY + wy) * MWZ + wz;
    int bwy = b * MPS + (wy * MWX + wx) * MWZ + wz;
    int vx = bwx * VOL + (cx * WIN_Y + cy) * WIN_Z + cz;
    int vy = bwy * VOL + (cy * WIN_X + cx) * WIN_Z + cz;
    g_vx[i] = vx;
    g_vy[i] = vy;
    if (vx >= 0 && vx < (int)KEYS) atomicOr(&g_bitX[vx >> 5], 1u << (vx & 31));
    if (vy >= 0 && vy < (int)KEYS) atomicOr(&g_bitY[vy >> 5], 1u << (vy & 31));
    int dst = Np + i;
    if (dst >= 0 && dst < out_size)
        out[dst] = (float)(i + (g_bsp[b] - g_bs[b]));
}

// flat2win value for padded index j.
__device__ __forceinline__ int f2w_val(int j, const int* s_bs, const int* s_bsp,
                                       const int* s_cnt, const int* s_cntp) {
    int b = 0;
#pragma unroll
    for (int k = 1; k < NB; k++) if (j >= s_bsp[k]) b = k;
    int off  = s_bsp[b] - s_bs[b];
    int num  = s_cnt[b];
    int nump = s_cntp[b];
    int r = num % G;
    int tail = (num != nump) ? (s_bsp[b + 1] - G + r) : s_bsp[b + 1];
    if (j < tail)  return j - off;
    if (nump != G) return j - G - off;
    int t = j - tail;
    int m = num > 0 ? num : 1;
    return s_bs[b] + t % m;
}

// flat2win: 4 consecutive j per thread, float4 stores.
__global__ void k_f2w(float* __restrict__ out, int out_size) {
    __shared__ int s_bs[NB + 1], s_bsp[NB + 1], s_cnt[NB], s_cntp[NB];
    if (threadIdx.x <= NB) {
        s_bs[threadIdx.x]  = g_bs[threadIdx.x];
        s_bsp[threadIdx.x] = g_bsp[threadIdx.x];
    }
    if (threadIdx.x < NB) {
        s_cnt[threadIdx.x]  = g_cnt[threadIdx.x];
        s_cntp[threadIdx.x] = g_cntp[threadIdx.x];
    }
    __syncthreads();
    int Np = s_bsp[NB];
    int lim = Np < out_size ? Np : out_size;
    int j0 = (blockIdx.x * blockDim.x + threadIdx.x) * 4;
    if (j0 >= lim) return;
    if (j0 + 3 < lim) {
        float4 r;
        r.x = (float)f2w_val(j0 + 0, s_bs, s_bsp, s_cnt, s_cntp);
        r.y = (float)f2w_val(j0 + 1, s_bs, s_bsp, s_cnt, s_cntp);
        r.z = (float)f2w_val(j0 + 2, s_bs, s_bsp, s_cnt, s_cntp);
        r.w = (float)f2w_val(j0 + 3, s_bs, s_bsp, s_cnt, s_cntp);
        reinterpret_cast<float4*>(out)[j0 >> 2] = r;
    } else {
        for (int j = j0; j < lim; j++)
            out[j] = (float)f2w_val(j, s_bs, s_bsp, s_cnt, s_cntp);
    }
}

// Scan pass 1: per-block popcount totals. gridDim.y selects X/Y map.
__global__ void k_scan1() {
    const uint32_t* bm = blockIdx.y ? g_bitY : g_bitX;
    uint32_t* bsum     = blockIdx.y ? g_bsumY : g_bsumX;
    int base = blockIdx.x * WPB + threadIdx.x * ITEMS;
    uint4 a = reinterpret_cast<const uint4*>(bm + base)[0];
    uint4 b = reinterpret_cast<const uint4*>(bm + base)[1];
    int s = __popc(a.x) + __popc(a.y) + __popc(a.z) + __popc(a.w)
          + __popc(b.x) + __popc(b.y) + __popc(b.z) + __popc(b.w);
    int lane = threadIdx.x & 31, warp = threadIdx.x >> 5;
#pragma unroll
    for (int d = 16; d; d >>= 1) s += __shfl_down_sync(0xFFFFFFFFu, s, d);
    __shared__ int ws[BLOCK / 32];
    if (lane == 0) ws[warp] = s;
    __syncthreads();
    if (threadIdx.x == 0) {
        int t = 0;
#pragma unroll
        for (int k = 0; k < BLOCK / 32; k++) t += ws[k];
        bsum[blockIdx.x] = (uint32_t)t;
    }
}

// Scan pass 2: PARALLEL exclusive scan of 2178 block sums. One block per map.
constexpr int S2T = 1024;
constexpr int S2C = (NBLK + S2T - 1) / S2T;  // 3 items per thread
__global__ void k_scan2p() {
    uint32_t* bsum = blockIdx.x ? g_bsumY : g_bsumX;
    int tid = threadIdx.x;
    int base = tid * S2C;

    uint32_t v[S2C];
    uint32_t ct = 0;
#pragma unroll
    for (int k = 0; k < S2C; k++) {
        int idx = base + k;
        v[k] = (idx < NBLK) ? bsum[idx] : 0u;
        ct += v[k];
    }

    int lane = tid & 31, warp = tid >> 5;
    uint32_t incl = ct;
#pragma unroll
    for (int d = 1; d < 32; d <<= 1) {
        uint32_t n = __shfl_up_sync(0xFFFFFFFFu, incl, d);
        if (lane >= d) incl += n;
    }
    __shared__ uint32_t wsum[S2T / 32];
    if (lane == 31) wsum[warp] = incl;
    __syncthreads();
    if (warp == 0) {
        uint32_t w = (lane < S2T / 32) ? wsum[lane] : 0u;
#pragma unroll
        for (int d = 1; d < 32; d <<= 1) {
            uint32_t n = __shfl_up_sync(0xFFFFFFFFu, w, d);
            if (lane >= d) w += n;
        }
        if (lane < S2T / 32) wsum[lane] = w;
    }
    __syncthreads();
    uint32_t excl = incl - ct + (warp ? wsum[warp - 1] : 0u);

#pragma unroll
    for (int k = 0; k < S2C; k++) {
        int idx = base + k;
        if (idx < NBLK) bsum[idx] = excl;
        excl += v[k];
    }
}

// Scan pass 3: per-word exclusive prefix; writes combined {bits, scan} and
// CLEARS the bitmap behind itself (restores zero invariant for next replay).
__global__ void k_scan3() {
    uint32_t* bm;
    uint2* cmb;
    const uint32_t* bsum;
    if (blockIdx.y) { bm = g_bitY; cmb = g_cmbY; bsum = g_bsumY; }
    else            { bm = g_bitX; cmb = g_cmbX; bsum = g_bsumX; }
    int base = blockIdx.x * WPB + threadIdx.x * ITEMS;
    uint4 a = reinterpret_cast<const uint4*>(bm + base)[0];
    uint4 b = reinterpret_cast<const uint4*>(bm + base)[1];
    int pc[8];
    pc[0] = __popc(a.x); pc[1] = __popc(a.y); pc[2] = __popc(a.z); pc[3] = __popc(a.w);
    pc[4] = __popc(b.x); pc[5] = __popc(b.y); pc[6] = __popc(b.z); pc[7] = __popc(b.w);
    int s = pc[0] + pc[1] + pc[2] + pc[3] + pc[4] + pc[5] + pc[6] + pc[7];

    int lane = threadIdx.x & 31, warp = threadIdx.x >> 5;
    int incl = s;
#pragma unroll
    for (int d = 1; d < 32; d <<= 1) {
        int n = __shfl_up_sync(0xFFFFFFFFu, incl, d);
        if (lane >= d) incl += n;
    }
    __shared__ int wsum[BLOCK / 32];
    if (lane == 31) wsum[warp] = incl;
    __syncthreads();
    int wofs = 0;
#pragma unroll
    for (int k = 0; k < BLOCK / 32; k++) if (k < warp) wofs += wsum[k];

    uint32_t excl = (uint32_t)(wofs + incl - s) + bsum[blockIdx.x];
    uint32_t w_[8] = {a.x, a.y, a.z, a.w, b.x, b.y, b.z, b.w};
#pragma unroll
    for (int k = 0; k < 8; k++) {
        cmb[base + k] = make_uint2(w_[k], excl);
        excl += pc[k];
    }
    // clear-behind: restore zero bitmap for the next graph replay
    uint4 z = make_uint4(0u, 0u, 0u, 0u);
    reinterpret_cast<uint4*>(bm + base)[0] = z;
    reinterpret_cast<uint4*>(bm + base)[1] = z;
}

// Rank via one fused gather per map, scatter argsort results (float).
// Layout: [ f2w(Np) | w2f(N) | xmap(N) | ymap(N) ].
__global__ void k_scatter(float* __restrict__ out, int out_size) {
    int i = blockIdx.x * blockDim.x + threadIdx.x;
    int N = g_N;
    if (i >= N) return;
    int Np = g_bsp[NB];
    float fi = (float)i;
    {
        int v = g_vx[i];
        int w = v >> 5, bit = v & 31;
        uint2 c = g_cmbX[w];
        int r = (int)c.y + __popc(c.x & ((1u << bit) - 1u));
        int dst = Np + N + r;
        if (dst >= 0 && dst < out_size) out[dst] = fi;
    }
    {
        int v = g_vy[i];
        int w = v >> 5, bit = v & 31;
        uint2 c = g_cmbY[w];
        int r = (int)c.y + __popc(c.x & ((1u << bit) - 1u));
        int dst = Np + 2 * N + r;
        if (dst >= 0 && dst < out_size) out[dst] = fi;
    }
}

// ---------------- Launch ----------------
extern "C" void kernel_launch(void* const* d_in, const int* in_sizes, int n_in,
                              void* d_out, int out_size) {
    int ci = 0;
    for (int k = 1; k < n_in; k++) if (in_sizes[k] > in_sizes[ci]) ci = k;
    const int* coords = (const int*)d_in[ci];
    int E = in_sizes[ci];

    int n_launch = E / 4;
    if (out_size / 4 > n_launch) n_launch = out_size / 4;
    if (n_launch < 1) n_launch = 1;
    if (n_launch > MAXN) n_launch = MAXN;

    float* out = (float*)d_out;
    int np_max = n_launch + NB * G;

    k_meta<<<1, BLOCK>>>(coords, E, out_size);
    k_tail<<<32, 256>>>(out, out_size);
    k_build<<<(n_launch + 255) / 256, 256>>>(coords, out, out_size);
    k_f2w<<<((np_max + 3) / 4 + 255) / 256, 256>>>(out, out_size);
    dim3 gscan(NBLK, 2);
    k_scan1<<<gscan, BLOCK>>>();
    k_scan2p<<<2, S2T>>>();
    k_scan3<<<gscan, BLOCK>>>();
    k_scatter<<<(n_launch + 255) / 256, 256>>>(out, out_size);
}

// round 17
// speedup vs baseline: 1.0941x; 1.0488x over previous
#include <cuda_runtime.h>
#include <stdint.h>

// ---------------- Problem constants (match reference setup) ----------------
constexpr int NB    = 8;
constexpr int G     = 69;
constexpr int WIN_X = 12, WIN_Y = 12, WIN_Z = 32;
constexpr int SHX = WIN_X / 2, SHY = WIN_Y / 2, SHZ = WIN_Z / 2;  // 6,6,16
constexpr int MWX = 44, MWY = 44, MWZ = 2;
constexpr int MPS = MWX * MWY * MWZ;            // 3872
constexpr int VOL = WIN_X * WIN_Y * WIN_Z;      // 4608

constexpr long long KEYS = (long long)NB * MPS * VOL;  // 142,737,408
constexpr int WORDS = (int)(KEYS / 32);                // 4,460,544

constexpr int BLOCK = 256;
constexpr int ITEMS = 8;
constexpr int WPB   = BLOCK * ITEMS;     // 2048 words per scan block
constexpr int NBLK  = WORDS / WPB;       // 2178 (exact)

constexpr int MAXN = 1 << 22;
constexpr int MAXC = 160;                // candidate window for N solver

// ---------------- Static device scratch (zero-initialized at load) --------
// Invariant: g_bitX/g_bitY all-zero on entry (zero-init at load; restored by
// k_scan3 clear-behind each run).
__device__ __align__(128) uint32_t g_bitX[WORDS];
__device__ __align__(128) uint32_t g_bitY[WORDS];
__device__ __align__(128) uint2    g_cmbX[WORDS];   // {bits, exclusive scan}
__device__ __align__(128) uint2    g_cmbY[WORDS];
__device__ uint32_t g_bsumX[NBLK];
__device__ uint32_t g_bsumY[NBLK];
__device__ int g_vx[MAXN];
__device__ int g_vy[MAXN];
__device__ int g_bs[NB + 1];
__device__ int g_bsp[NB + 1];
__device__ int g_cnt[NB];
__device__ int g_cntp[NB];
__device__ int g_N;
__device__ int g_is64;

// ---------------- Kernels ----------------

__device__ __forceinline__ int ld_batch(const int* c32, int m, bool is64) {
    return is64 ? c32[8 * m] : c32[4 * m];
}

// Detect coords dtype, then solve N from out_size == Np(N) + 3N.
__global__ void k_meta(const int* __restrict__ c32, int E, int out_size) {
    __shared__ int sh_bs[MAXC][NB];
    __shared__ uint32_t s_orr;
    __shared__ int s_is64;
    int tid = threadIdx.x;

    if (tid == 0) s_orr = 0u;
    __syncthreads();
    {
        int rows = E / 8;
        if (rows > 2048) rows = 2048;
        uint32_t orr = 0;
        for (int t = tid; t < rows * 4; t += BLOCK)
            orr |= (uint32_t)c32[2 * t + 1];
        atomicOr(&s_orr, orr);
    }
    __syncthreads();
    if (tid == 0) s_is64 = (s_orr == 0u) ? 1 : 0;
    __syncthreads();
    bool is64 = (s_is64 != 0);

    int n_std = E / 4;
    if (n_std < 1) n_std = 1;
    if (n_std > MAXN) n_std = MAXN;

    int hi = out_size / 4;
    if (hi > MAXN) hi = MAXN;
    if (hi < 1) hi = 1;
    int lo = hi - (MAXC - 2);
    if (lo < 1) lo = 1;
    int ncand = hi - lo + 1;               // slot ncand = n_std

    for (int t = tid; t < (ncand + 1) * NB; t += BLOCK) {
        int c = t >> 3, b = t & 7;
        int cand = (c == ncand) ? n_std : (lo + c);
        int l = 0, h = cand;
        while (l < h) {
            int m = (l + h) >> 1;
            if (ld_batch(c32, m, is64) < b) l = m + 1; else h = m;
        }
        sh_bs[c][b] = l;
    }
    __syncthreads();

    if (tid == 0) {
        g_is64 = s_is64;
        int sel = ncand, selN = n_std;
        long long fstd = 0;
        for (int b = 0; b < NB; b++) {
            int e = (b == NB - 1) ? n_std : sh_bs[ncand][b + 1];
            int cnt = e - sh_bs[ncand][b];
            fstd += ((cnt + G - 1) / G) * (long long)G;
        }
        fstd += 3LL * n_std;
        if (fstd != out_size) {
            for (int c = ncand - 1; c >= 0; c--) {
                int cand = lo + c;
                long long f = 0;
                for (int b = 0; b < NB; b++) {
                    int e = (b == NB - 1) ? cand : sh_bs[c][b + 1];
                    int cnt = e - sh_bs[c][b];
                    f += ((cnt + G - 1) / G) * (long long)G;
                }
                f += 3LL * cand;
                if (f == out_size) { sel = c; selN = cand; break; }
            }
        }
        g_N = selN;
        int acc = 0;
        g_bsp[0] = 0;
        for (int b = 0; b < NB; b++) {
            int s = sh_bs[sel][b];
            int e = (b == NB - 1) ? selN : sh_bs[sel][b + 1];
            g_bs[b] = s;
            int c = e - s;
            g_cnt[b] = c;
            int cp = ((c + G - 1) / G) * G;
            g_cntp[b] = cp;
            acc += cp;
            g_bsp[b + 1] = acc;
        }
        g_bs[NB] = selN;
    }
}

// flat2win value for padded index j.
__device__ __forceinline__ int f2w_val(int j, const int* s_bs, const int* s_bsp,
                                       const int* s_cnt, const int* s_cntp) {
    int b = 0;
#pragma unroll
    for (int k = 1; k < NB; k++) if (j >= s_bsp[k]) b = k;
    int off  = s_bsp[b] - s_bs[b];
    int num  = s_cnt[b];
    int nump = s_cntp[b];
    int r = num % G;
    int tail = (num != nump) ? (s_bsp[b + 1] - G + r) : s_bsp[b + 1];
    if (j < tail)  return j - off;
    if (nump != G) return j - G - off;
    int t = j - tail;
    int m = num > 0 ? num : 1;
    return s_bs[b] + t % m;
}

// FUSED mid-stage: build (keys+bitmap+win2flat) | f2w | tail padding.
// All three depend only on k_meta and are mutually independent, so they share
// one launch; f2w's ALU work hides under build's L2-atomic-bound memory stalls.
__global__ void k_fused(const int* __restrict__ c32, float* __restrict__ out,
                        int out_size, int nb_build, int nb_f2w) {
    int bx = blockIdx.x;

    if (bx < nb_build) {
        // ----- build -----
        int i = bx * BLOCK + threadIdx.x;
        int N = g_N;
        if (i >= N) return;
        int Np = g_bsp[NB];
        int b, z, y, x;
        if (g_is64) {
            const int* p = c32 + 8 * i;
            b = p[0]; z = p[2]; y = p[4]; x = p[6];
        } else {
            int4 c = reinterpret_cast<const int4*>(c32)[i];
            b = c.x; z = c.y; y = c.z; x = c.w;
        }
        z += SHZ; y += SHY; x += SHX;
        int wx = x / WIN_X, cx = x - wx * WIN_X;
        int wy = y / WIN_Y, cy = y - wy * WIN_Y;
        int wz = z >> 5,    cz = z & 31;
        int bwx = b * MPS + (wx * MWY + wy) * MWZ + wz;
        int bwy = b * MPS + (wy * MWX + wx) * MWZ + wz;
        int vx = bwx * VOL + (cx * WIN_Y + cy) * WIN_Z + cz;
        int vy = bwy * VOL + (cy * WIN_X + cx) * WIN_Z + cz;
        g_vx[i] = vx;
        g_vy[i] = vy;
        if (vx >= 0 && vx < (int)KEYS) atomicOr(&g_bitX[vx >> 5], 1u << (vx & 31));
        if (vy >= 0 && vy < (int)KEYS) atomicOr(&g_bitY[vy >> 5], 1u << (vy & 31));
        int dst = Np + i;
        if (dst >= 0 && dst < out_size)
            out[dst] = (float)(i + (g_bsp[b] - g_bs[b]));
    } else if (bx < nb_build + nb_f2w) {
        // ----- flat2win (4 j per thread, float4 stores) -----
        __shared__ int s_bs[NB + 1], s_bsp[NB + 1], s_cnt[NB], s_cntp[NB];
        if (threadIdx.x <= NB) {
            s_bs[threadIdx.x]  = g_bs[threadIdx.x];
            s_bsp[threadIdx.x] = g_bsp[threadIdx.x];
        }
        if (threadIdx.x < NB) {
            s_cnt[threadIdx.x]  = g_cnt[threadIdx.x];
            s_cntp[threadIdx.x] = g_cntp[threadIdx.x];
        }
        __syncthreads();
        int Np = s_bsp[NB];
        int lim = Np < out_size ? Np : out_size;
        int j0 = ((bx - nb_build) * BLOCK + threadIdx.x) * 4;
        if (j0 >= lim) return;
        if (j0 + 3 < lim) {
            float4 r;
            r.x = (float)f2w_val(j0 + 0, s_bs, s_bsp, s_cnt, s_cntp);
            r.y = (float)f2w_val(j0 + 1, s_bs, s_bsp, s_cnt, s_cntp);
            r.z = (float)f2w_val(j0 + 2, s_bs, s_bsp, s_cnt, s_cntp);
            r.w = (float)f2w_val(j0 + 3, s_bs, s_bsp, s_cnt, s_cntp);
            reinterpret_cast<float4*>(out)[j0 >> 2] = r;
        } else {
            for (int j = j0; j < lim; j++)
                out[j] = (float)f2w_val(j, s_bs, s_bsp, s_cnt, s_cntp);
        }
    } else {
        // ----- tail: zero output padding beyond Np + 3N (normally empty) ---
        int end = g_bsp[NB] + 3 * g_N;
        int tb = bx - nb_build - nb_f2w;
        for (int i = end + tb * BLOCK + threadIdx.x; i < out_size;
             i += 32 * BLOCK)
            out[i] = 0.0f;
    }
}

// Scan pass 1: per-block popcount totals. gridDim.y selects X/Y map.
__global__ void k_scan1() {
    const uint32_t* bm = blockIdx.y ? g_bitY : g_bitX;
    uint32_t* bsum     = blockIdx.y ? g_bsumY : g_bsumX;
    int base = blockIdx.x * WPB + threadIdx.x * ITEMS;
    uint4 a = reinterpret_cast<const uint4*>(bm + base)[0];
    uint4 b = reinterpret_cast<const uint4*>(bm + base)[1];
    int s = __popc(a.x) + __popc(a.y) + __popc(a.z) + __popc(a.w)
          + __popc(b.x) + __popc(b.y) + __popc(b.z) + __popc(b.w);
    int lane = threadIdx.x & 31, warp = threadIdx.x >> 5;
#pragma unroll
    for (int d = 16; d; d >>= 1) s += __shfl_down_sync(0xFFFFFFFFu, s, d);
    __shared__ int ws[BLOCK / 32];
    if (lane == 0) ws[warp] = s;
    __syncthreads();
    if (threadIdx.x == 0) {
        int t = 0;
#pragma unroll
        for (int k = 0; k < BLOCK / 32; k++) t += ws[k];
        bsum[blockIdx.x] = (uint32_t)t;
    }
}

// Scan pass 2: PARALLEL exclusive scan of 2178 block sums. One block per map.
constexpr int S2T = 1024;
constexpr int S2C = (NBLK + S2T - 1) / S2T;  // 3 items per thread
__global__ void k_scan2p() {
    uint32_t* bsum = blockIdx.x ? g_bsumY : g_bsumX;
    int tid = threadIdx.x;
    int base = tid * S2C;

    uint32_t v[S2C];
    uint32_t ct = 0;
#pragma unroll
    for (int k = 0; k < S2C; k++) {
        int idx = base + k;
        v[k] = (idx < NBLK) ? bsum[idx] : 0u;
        ct += v[k];
    }

    int lane = tid & 31, warp = tid >> 5;
    uint32_t incl = ct;
#pragma unroll
    for (int d = 1; d < 32; d <<= 1) {
        uint32_t n = __shfl_up_sync(0xFFFFFFFFu, incl, d);
        if (lane >= d) incl += n;
    }
    __shared__ uint32_t wsum[S2T / 32];
    if (lane == 31) wsum[warp] = incl;
    __syncthreads();
    if (warp == 0) {
        uint32_t w = (lane < S2T / 32) ? wsum[lane] : 0u;
#pragma unroll
        for (int d = 1; d < 32; d <<= 1) {
            uint32_t n = __shfl_up_sync(0xFFFFFFFFu, w, d);
            if (lane >= d) w += n;
        }
        if (lane < S2T / 32) wsum[lane] = w;
    }
    __syncthreads();
    uint32_t excl = incl - ct + (warp ? wsum[warp - 1] : 0u);

#pragma unroll
    for (int k = 0; k < S2C; k++) {
        int idx = base + k;
        if (idx < NBLK) bsum[idx] = excl;
        excl += v[k];
    }
}

// Scan pass 3: per-word exclusive prefix; writes combined {bits, scan} and
// CLEARS the bitmap behind itself (restores zero invariant for next replay).
__global__ void k_scan3() {
    uint32_t* bm;
    uint2* cmb;
    const uint32_t* bsum;
    if (blockIdx.y) { bm = g_bitY; cmb = g_cmbY; bsum = g_bsumY; }
    else            { bm = g_bitX; cmb = g_cmbX; bsum = g_bsumX; }
    int base = blockIdx.x * WPB + threadIdx.x * ITEMS;
    uint4 a = reinterpret_cast<const uint4*>(bm + base)[0];
    uint4 b = reinterpret_cast<const uint4*>(bm + base)[1];
    int pc[8];
    pc[0] = __popc(a.x); pc[1] = __popc(a.y); pc[2] = __popc(a.z); pc[3] = __popc(a.w);
    pc[4] = __popc(b.x); pc[5] = __popc(b.y); pc[6] = __popc(b.z); pc[7] = __popc(b.w);
    int s = pc[0] + pc[1] + pc[2] + pc[3] + pc[4] + pc[5] + pc[6] + pc[7];

    int lane = threadIdx.x & 31, warp = threadIdx.x >> 5;
    int incl = s;
#pragma unroll
    for (int d = 1; d < 32; d <<= 1) {
        int n = __shfl_up_sync(0xFFFFFFFFu, incl, d);
        if (lane >= d) incl += n;
    }
    __shared__ int wsum[BLOCK / 32];
    if (lane == 31) wsum[warp] = incl;
    __syncthreads();
    int wofs = 0;
#pragma unroll
    for (int k = 0; k < BLOCK / 32; k++) if (k < warp) wofs += wsum[k];

    uint32_t excl = (uint32_t)(wofs + incl - s) + bsum[blockIdx.x];
    uint32_t w_[8] = {a.x, a.y, a.z, a.w, b.x, b.y, b.z, b.w};
#pragma unroll
    for (int k = 0; k < 8; k++) {
        cmb[base + k] = make_uint2(w_[k], excl);
        excl += pc[k];
    }
    // clear-behind: restore zero bitmap for the next graph replay
    uint4 z = make_uint4(0u, 0u, 0u, 0u);
    reinterpret_cast<uint4*>(bm + base)[0] = z;
    reinterpret_cast<uint4*>(bm + base)[1] = z;
}

// Rank via one fused gather per map, scatter argsort results (float).
// Layout: [ f2w(Np) | w2f(N) | xmap(N) | ymap(N) ].
__global__ void k_scatter(float* __restrict__ out, int out_size) {
    int i = blockIdx.x * blockDim.x + threadIdx.x;
    int N = g_N;
    if (i >= N) return;
    int Np = g_bsp[NB];
    float fi = (float)i;
    {
        int v = g_vx[i];
        int w = v >> 5, bit = v & 31;
        uint2 c = g_cmbX[w];
        int r = (int)c.y + __popc(c.x & ((1u << bit) - 1u));
        int dst = Np + N + r;
        if (dst >= 0 && dst < out_size) out[dst] = fi;
    }
    {
        int v = g_vy[i];
        int w = v >> 5, bit = v & 31;
        uint2 c = g_cmbY[w];
        int r = (int)c.y + __popc(c.x & ((1u << bit) - 1u));
        int dst = Np + 2 * N + r;
        if (dst >= 0 && dst < out_size) out[dst] = fi;
    }
}

// ---------------- Launch ----------------
extern "C" void kernel_launch(void* const* d_in, const int* in_sizes, int n_in,
                              void* d_out, int out_size) {
    int ci = 0;
    for (int k = 1; k < n_in; k++) if (in_sizes[k] > in_sizes[ci]) ci = k;
    const int* coords = (const int*)d_in[ci];
    int E = in_sizes[ci];

    int n_launch = E / 4;
    if (out_size / 4 > n_launch) n_launch = out_size / 4;
    if (n_launch < 1) n_launch = 1;
    if (n_launch > MAXN) n_launch = MAXN;

    float* out = (float*)d_out;
    int np_max = n_launch + NB * G;

    int nb_build = (n_launch + BLOCK - 1) / BLOCK;
    int nb_f2w   = ((np_max + 3) / 4 + BLOCK - 1) / BLOCK;
    int nb_tail  = 32;

    k_meta<<<1, BLOCK>>>(coords, E, out_size);
    k_fused<<<nb_build + nb_f2w + nb_tail, BLOCK>>>(coords, out, out_size,
                                                    nb_build, nb_f2w);
    dim3 gscan(NBLK, 2);
    k_scan1<<<gscan, BLOCK>>>();
    k_scan2p<<<2, S2T>>>();
    k_scan3<<<gscan, BLOCK>>>();
    k_scatter<<<(n_launch + 255) / 256, 256>>>(out, out_size);
}